// round 2
// baseline (speedup 1.0000x reference)
#include <cuda_runtime.h>

typedef unsigned long long ull;
#define FEATC 268
#define KPAD  272

// ---------------- scratch: __device__ globals (no allocations) ----------------
__device__ float g_geom[(size_t)800000 * 12];  // radial,dist,dot,so3(9) per edge
__device__ float g_W1T[KPAD * 128];            // layer1 weights [f][n], heads concat, padded
__device__ float g_W2c[128 * 128];             // dense block-diag layer2 weights [k][n]
__device__ float g_agg[(size_t)50000 * 128];   // segment_sum(edge_feat)
__device__ float g_cacc[(size_t)50000 * 3];    // segment_sum(trans)

// ---------------- packed f32x2 helpers ----------------
__device__ __forceinline__ void fma2(ull& d, ull a, ull b) {
    asm("fma.rn.f32x2 %0, %1, %2, %0;" : "+l"(d) : "l"(a), "l"(b));
}
__device__ __forceinline__ ull bcast2(float x) {
    ull r; asm("mov.b64 %0, {%1, %1};" : "=l"(r) : "f"(x)); return r;
}
__device__ __forceinline__ ull pk2(float a, float b) {
    ull r; asm("mov.b64 %0, {%1, %2};" : "=l"(r) : "f"(a), "f"(b)); return r;
}
__device__ __forceinline__ float2 up2(ull v) {
    float2 f; asm("mov.b64 {%0, %1}, %2;" : "=f"(f.x), "=f"(f.y) : "l"(v)); return f;
}
__device__ __forceinline__ float silu_f(float x) { return x / (1.f + __expf(-x)); }

// ---- 8x8 micro-kernel: A k-major [8][128], B k-major [8][128] (one 8-k slab) ----
__device__ __forceinline__ void mm8(const float* __restrict__ A, const float* __restrict__ B,
                                    int m0, int n0, ull acc[8][4]) {
#pragma unroll
    for (int kk = 0; kk < 8; kk++) {
        const ull* bp = (const ull*)(B + kk * 128 + n0);
        ull b0 = bp[0], b1 = bp[1], b2 = bp[2], b3 = bp[3];
        float4 a0 = *(const float4*)(A + kk * 128 + m0);
        float4 a1 = *(const float4*)(A + kk * 128 + m0 + 4);
        float av[8] = {a0.x, a0.y, a0.z, a0.w, a1.x, a1.y, a1.z, a1.w};
#pragma unroll
        for (int i = 0; i < 8; i++) {
            ull ap = bcast2(av[i]);
            fma2(acc[i][0], ap, b0); fma2(acc[i][1], ap, b1);
            fma2(acc[i][2], ap, b2); fma2(acc[i][3], ap, b3);
        }
    }
}

// ---- same but A row-major pitch 132 (k window at k0), B k-major [128][128] ----
__device__ __forceinline__ void mm8_rm(const float* __restrict__ A, const float* __restrict__ B,
                                       int m0, int n0, int k0, ull acc[8][4]) {
#pragma unroll
    for (int kk = 0; kk < 8; kk++) {
        int k = k0 + kk;
        const ull* bp = (const ull*)(B + k * 128 + n0);
        ull b0 = bp[0], b1 = bp[1], b2 = bp[2], b3 = bp[3];
#pragma unroll
        for (int i = 0; i < 8; i++) {
            ull ap = bcast2(A[(m0 + i) * 132 + k]);
            fma2(acc[i][0], ap, b0); fma2(acc[i][1], ap, b1);
            fma2(acc[i][2], ap, b2); fma2(acc[i][3], ap, b3);
        }
    }
}

// ---------------- prep: transpose eW1 -> [f][n]; densify eW2 block-diag ----------------
__global__ void prep_kernel(const float* __restrict__ eW1, const float* __restrict__ eW2) {
    int i = blockIdx.x * blockDim.x + threadIdx.x;
    if (i < KPAD * 128) {
        int f = i >> 7, n = i & 127;
        g_W1T[i] = (f < FEATC) ? eW1[(size_t)(n >> 5) * FEATC * 32 + (size_t)f * 32 + (n & 31)] : 0.f;
    }
    if (i < 128 * 128) {
        int k = i >> 7, n = i & 127;
        g_W2c[i] = ((k >> 5) == (n >> 5)) ? eW2[(k >> 5) * 1024 + (k & 31) * 32 + (n & 31)] : 0.f;
    }
}

__global__ void zero_kernel(int N) {
    int total = N * 128 + N * 3;
    for (int i = blockIdx.x * blockDim.x + threadIdx.x; i < total; i += gridDim.x * blockDim.x) {
        if (i < N * 128) g_agg[i] = 0.f;
        else g_cacc[i - N * 128] = 0.f;
    }
}

// ---------------- per-edge geometry ----------------
__global__ void geom_kernel(const float* __restrict__ coord, const int* __restrict__ ei, int E) {
    int e = blockIdx.x * blockDim.x + threadIdx.x;
    if (e >= E) return;
    int r = ei[e], c = ei[E + e];
    float cix = coord[r * 3], ciy = coord[r * 3 + 1], ciz = coord[r * 3 + 2];
    float ckx = coord[c * 3], cky = coord[c * 3 + 1], ckz = coord[c * 3 + 2];
    float dx = cix - ckx, dy = ciy - cky, dz = ciz - ckz;
    float radial = dx * dx + dy * dy + dz * dz;
    float dist = sqrtf(radial);
    float dotv = cix * ckx + ciy * cky + ciz * ckz;
    float inva = 1.f / (dist + 1e-8f);
    float ax = dx * inva, ay = dy * inva, az = dz * inva;
    float px = ciy * ckz - ciz * cky;
    float py = ciz * ckx - cix * ckz;
    float pz = cix * cky - ciy * ckx;
    float nb = sqrtf(px * px + py * py + pz * pz);
    float invb = 1.f / (nb + 1e-8f);
    float bx = px * invb, by = py * invb, bz = pz * invb;
    float cx = ay * bz - az * by;
    float cy = az * bx - ax * bz;
    float cz = ax * by - ay * bx;
    float na_n = sqrtf(ax * ax + ay * ay + az * az);
    float nb_n = sqrtf(bx * bx + by * by + bz * bz);
    float nc_n = sqrtf(cx * cx + cy * cy + cz * cz);
    if ((na_n < 1e-6f) || (nb_n < 1e-6f) || (nc_n < 1e-6f)) {
        ax = 1.f; ay = 0.f; az = 0.f; bx = 0.f; by = 1.f; bz = 0.f; cx = 0.f; cy = 0.f; cz = 1.f;
    }
    float* g = g_geom + (size_t)e * 12;
    g[0] = radial; g[1] = dist; g[2] = dotv;
    g[3] = ax; g[4] = bx; g[5] = cx;
    g[6] = ay; g[7] = by; g[8] = cy;
    g[9] = az; g[10] = bz; g[11] = cz;
}

// ---------------- edge mega-kernel ----------------
// smem floats: As[1024] Bs[1024] xb[128*132] B2[128*128] rS[128*17] rQ[128*17]
//              erow[128]i ecol[128]i cw2s[128]  -> 40064 words = 160256 B
#define EDGE_SMEM_BYTES (40064 * 4)
__global__ void __launch_bounds__(256, 1)
edge_kernel(const float* __restrict__ h, const float* __restrict__ coord,
            const int* __restrict__ ei,
            const float* __restrict__ eb1, const float* __restrict__ eb2,
            const float* __restrict__ lng, const float* __restrict__ lnb,
            const float* __restrict__ cW1, const float* __restrict__ cb1,
            const float* __restrict__ cW2, int E) {
    extern __shared__ float sm[];
    float* As = sm;
    float* Bs = sm + 1024;
    float* xb = sm + 2048;          // [128][132] row-major
    float* B2 = sm + 18944;         // [128][128]
    float* rS = sm + 35328;         // [128][17]
    float* rQ = sm + 37504;
    int*  erow = (int*)(sm + 39680);
    int*  ecol = erow + 128;
    float* cw2s = sm + 39936;

    int tid = threadIdx.x;
    int tx = tid & 15, ty = tid >> 4;
    int m0 = ty * 8, n0 = tx * 8;
    int e0 = blockIdx.x * 128;

    if (tid < 128) {
        int e = min(e0 + tid, E - 1);
        erow[tid] = ei[e];
        ecol[tid] = ei[E + e];
        cw2s[tid] = cW2[tid];
    }
    for (int i = tid; i < 16384; i += 256) B2[i] = g_W2c[i];
    __syncthreads();

    int rowm = 0, colm = 0; size_t egm = 0;
    if (tid < 128) { rowm = erow[tid]; colm = ecol[tid]; egm = (size_t)min(e0 + tid, E - 1); }

    ull acc[8][4];
#pragma unroll
    for (int i = 0; i < 8; i++) { acc[i][0] = acc[i][1] = acc[i][2] = acc[i][3] = 0ULL; }

    // ---- GEMM1: feats[128,272] x W1T[272,128] ----
    for (int s = 0; s < KPAD / 8; s++) {
        int k0 = s * 8;
        float lr[8];
        if (tid < 128) {
            if (k0 < 256) {
                const float* base = (k0 < 128) ? (h + (size_t)rowm * 128 + k0)
                                               : (h + (size_t)colm * 128 + (k0 - 128));
                float4 v0 = ((const float4*)base)[0];
                float4 v1 = ((const float4*)base)[1];
                lr[0] = v0.x; lr[1] = v0.y; lr[2] = v0.z; lr[3] = v0.w;
                lr[4] = v1.x; lr[5] = v1.y; lr[6] = v1.z; lr[7] = v1.w;
            } else {
#pragma unroll
                for (int kk = 0; kk < 8; kk++) {
                    int f = k0 + kk;
                    lr[kk] = (f < FEATC) ? g_geom[egm * 12 + (f - 256)] : 0.f;
                }
            }
        } else {
            int n = tid - 128;
#pragma unroll
            for (int kk = 0; kk < 8; kk++) lr[kk] = g_W1T[(k0 + kk) * 128 + n];
        }
        __syncthreads();
        {
            float* dst = (tid < 128) ? As : Bs;
            int o = tid & 127;
#pragma unroll
            for (int kk = 0; kk < 8; kk++) dst[kk * 128 + o] = lr[kk];
        }
        __syncthreads();
        mm8(As, Bs, m0, n0, acc);
    }
    // x1 = silu(acc + eb1) -> xb row-major
#pragma unroll
    for (int i = 0; i < 8; i++) {
        float4 w0, w1;
        float2 v0 = up2(acc[i][0]), v1 = up2(acc[i][1]), v2 = up2(acc[i][2]), v3 = up2(acc[i][3]);
        w0.x = silu_f(v0.x + eb1[n0 + 0]); w0.y = silu_f(v0.y + eb1[n0 + 1]);
        w0.z = silu_f(v1.x + eb1[n0 + 2]); w0.w = silu_f(v1.y + eb1[n0 + 3]);
        w1.x = silu_f(v2.x + eb1[n0 + 4]); w1.y = silu_f(v2.y + eb1[n0 + 5]);
        w1.z = silu_f(v3.x + eb1[n0 + 6]); w1.w = silu_f(v3.y + eb1[n0 + 7]);
        *(float4*)(xb + (m0 + i) * 132 + n0) = w0;
        *(float4*)(xb + (m0 + i) * 132 + n0 + 4) = w1;
    }
    __syncthreads();

    // ---- GEMM2 (dense block-diag W2) ----
#pragma unroll
    for (int i = 0; i < 8; i++) { acc[i][0] = acc[i][1] = acc[i][2] = acc[i][3] = 0ULL; }
    for (int k0 = 0; k0 < 128; k0 += 8) mm8_rm(xb, B2, m0, n0, k0, acc);

    // add eb2, accumulate LN stats, keep biased values packed in acc
#pragma unroll
    for (int i = 0; i < 8; i++) {
        float s_ = 0.f, q_ = 0.f;
#pragma unroll
        for (int jp = 0; jp < 4; jp++) {
            float2 v = up2(acc[i][jp]);
            float a0 = v.x + eb2[n0 + 2 * jp];
            float a1 = v.y + eb2[n0 + 2 * jp + 1];
            acc[i][jp] = pk2(a0, a1);
            s_ += a0 + a1; q_ += a0 * a0 + a1 * a1;
        }
        rS[(m0 + i) * 17 + tx] = s_;
        rQ[(m0 + i) * 17 + tx] = q_;
    }
    __syncthreads();

    // ---- LayerNorm -> xb (+ agg atomics), reload B2 <- cW1 ----
#pragma unroll
    for (int i = 0; i < 8; i++) {
        float s_ = 0.f, q_ = 0.f;
#pragma unroll
        for (int t = 0; t < 16; t++) { s_ += rS[(m0 + i) * 17 + t]; q_ += rQ[(m0 + i) * 17 + t]; }
        float mu = s_ * (1.f / 128.f);
        float var = q_ * (1.f / 128.f) - mu * mu;
        float rstd = rsqrtf(var + 1e-5f);
        float vals[8];
#pragma unroll
        for (int jp = 0; jp < 4; jp++) {
            float2 v = up2(acc[i][jp]);
            int na = n0 + 2 * jp, nb = na + 1;
            vals[2 * jp]     = (v.x - mu) * rstd * lng[na] + lnb[na];
            vals[2 * jp + 1] = (v.y - mu) * rstd * lng[nb] + lnb[nb];
        }
        *(float4*)(xb + (m0 + i) * 132 + n0)     = make_float4(vals[0], vals[1], vals[2], vals[3]);
        *(float4*)(xb + (m0 + i) * 132 + n0 + 4) = make_float4(vals[4], vals[5], vals[6], vals[7]);
        if (e0 + m0 + i < E) {
            size_t rbase = (size_t)erow[m0 + i] * 128 + n0;
#pragma unroll
            for (int j = 0; j < 8; j++) atomicAdd(&g_agg[rbase + j], vals[j]);
        }
    }
    for (int i = tid; i < 16384; i += 256) B2[i] = cW1[i];
    __syncthreads();

    // ---- GEMM3: hid = edge_feat @ cW1 ; w = silu(hid+cb1) . cW2 ----
#pragma unroll
    for (int i = 0; i < 8; i++) { acc[i][0] = acc[i][1] = acc[i][2] = acc[i][3] = 0ULL; }
    for (int k0 = 0; k0 < 128; k0 += 8) mm8_rm(xb, B2, m0, n0, k0, acc);
#pragma unroll
    for (int i = 0; i < 8; i++) {
        float p = 0.f;
#pragma unroll
        for (int jp = 0; jp < 4; jp++) {
            float2 v = up2(acc[i][jp]);
            int na = n0 + 2 * jp, nb = na + 1;
            p += silu_f(v.x + cb1[na]) * cw2s[na];
            p += silu_f(v.y + cb1[nb]) * cw2s[nb];
        }
        rS[(m0 + i) * 17 + tx] = p;
    }
    __syncthreads();
    if (tid < 128 && e0 + tid < E) {
        float w = 0.f;
#pragma unroll
        for (int t = 0; t < 16; t++) w += rS[tid * 17 + t];
        int r = erow[tid], c = ecol[tid];
        float dx = coord[r * 3]     - coord[c * 3];
        float dy = coord[r * 3 + 1] - coord[c * 3 + 1];
        float dz = coord[r * 3 + 2] - coord[c * 3 + 2];
        atomicAdd(&g_cacc[r * 3 + 0], dx * w);
        atomicAdd(&g_cacc[r * 3 + 1], dy * w);
        atomicAdd(&g_cacc[r * 3 + 2], dz * w);
    }
}

// ---------------- node kernel: h_out = h + MLP([h, agg]) ----------------
// smem floats: As[1024] Bs[1024] xb[128*132] B2[128*128] = 35328 words
#define NODE_SMEM_BYTES (35328 * 4)
__global__ void __launch_bounds__(256, 1)
node_kernel(const float* __restrict__ h,
            const float* __restrict__ nW1, const float* __restrict__ nb1,
            const float* __restrict__ nW2, const float* __restrict__ nb2,
            float* __restrict__ out, int N) {
    extern __shared__ float sm[];
    float* As = sm;
    float* Bs = sm + 1024;
    float* xb = sm + 2048;
    float* B2 = sm + 18944;

    int tid = threadIdx.x;
    int tx = tid & 15, ty = tid >> 4;
    int m0 = ty * 8, n0 = tx * 8;
    int v0base = blockIdx.x * 128;

    for (int i = tid; i < 16384; i += 256) B2[i] = nW2[i];

    size_t node = (size_t)min(v0base + (tid & 127), N - 1);

    ull acc[8][4];
#pragma unroll
    for (int i = 0; i < 8; i++) { acc[i][0] = acc[i][1] = acc[i][2] = acc[i][3] = 0ULL; }

    for (int s = 0; s < 32; s++) {
        int k0 = s * 8;
        float lr[8];
        if (tid < 128) {
            const float* base = (k0 < 128) ? (h + node * 128 + k0)
                                           : (g_agg + node * 128 + (k0 - 128));
            float4 v0 = ((const float4*)base)[0];
            float4 v1 = ((const float4*)base)[1];
            lr[0] = v0.x; lr[1] = v0.y; lr[2] = v0.z; lr[3] = v0.w;
            lr[4] = v1.x; lr[5] = v1.y; lr[6] = v1.z; lr[7] = v1.w;
        } else {
            int n = tid - 128;
#pragma unroll
            for (int kk = 0; kk < 8; kk++) lr[kk] = nW1[(k0 + kk) * 128 + n];
        }
        __syncthreads();
        {
            float* dst = (tid < 128) ? As : Bs;
            int o = tid & 127;
#pragma unroll
            for (int kk = 0; kk < 8; kk++) dst[kk * 128 + o] = lr[kk];
        }
        __syncthreads();
        mm8(As, Bs, m0, n0, acc);
    }
#pragma unroll
    for (int i = 0; i < 8; i++) {
        float4 w0, w1;
        float2 v0 = up2(acc[i][0]), v1 = up2(acc[i][1]), v2 = up2(acc[i][2]), v3 = up2(acc[i][3]);
        w0.x = silu_f(v0.x + nb1[n0 + 0]); w0.y = silu_f(v0.y + nb1[n0 + 1]);
        w0.z = silu_f(v1.x + nb1[n0 + 2]); w0.w = silu_f(v1.y + nb1[n0 + 3]);
        w1.x = silu_f(v2.x + nb1[n0 + 4]); w1.y = silu_f(v2.y + nb1[n0 + 5]);
        w1.z = silu_f(v3.x + nb1[n0 + 6]); w1.w = silu_f(v3.y + nb1[n0 + 7]);
        *(float4*)(xb + (m0 + i) * 132 + n0) = w0;
        *(float4*)(xb + (m0 + i) * 132 + n0 + 4) = w1;
    }
    __syncthreads();

#pragma unroll
    for (int i = 0; i < 8; i++) { acc[i][0] = acc[i][1] = acc[i][2] = acc[i][3] = 0ULL; }
    for (int k0 = 0; k0 < 128; k0 += 8) mm8_rm(xb, B2, m0, n0, k0, acc);

#pragma unroll
    for (int i = 0; i < 8; i++) {
        int nd = v0base + m0 + i;
        if (nd >= N) continue;
        float4 h0 = *(const float4*)(h + (size_t)nd * 128 + n0);
        float4 h1 = *(const float4*)(h + (size_t)nd * 128 + n0 + 4);
        float2 v0 = up2(acc[i][0]), v1 = up2(acc[i][1]), v2 = up2(acc[i][2]), v3 = up2(acc[i][3]);
        float4 o0, o1;
        o0.x = v0.x + nb2[n0 + 0] + h0.x; o0.y = v0.y + nb2[n0 + 1] + h0.y;
        o0.z = v1.x + nb2[n0 + 2] + h0.z; o0.w = v1.y + nb2[n0 + 3] + h0.w;
        o1.x = v2.x + nb2[n0 + 4] + h1.x; o1.y = v2.y + nb2[n0 + 5] + h1.y;
        o1.z = v3.x + nb2[n0 + 6] + h1.z; o1.w = v3.y + nb2[n0 + 7] + h1.w;
        *(float4*)(out + (size_t)nd * 128 + n0)     = o0;
        *(float4*)(out + (size_t)nd * 128 + n0 + 4) = o1;
    }
}

__global__ void coordout_kernel(const float* __restrict__ coord, float* __restrict__ out, int N) {
    int i = blockIdx.x * blockDim.x + threadIdx.x;
    if (i < 3 * N) out[i] = coord[i] + g_cacc[i];
}

extern "C" void kernel_launch(void* const* d_in, const int* in_sizes, int n_in,
                              void* d_out, int out_size) {
    const float* h     = (const float*)d_in[0];
    const float* coord = (const float*)d_in[1];
    const int*   ei    = (const int*)d_in[2];
    const float* eW1   = (const float*)d_in[3];
    const float* eb1   = (const float*)d_in[4];
    const float* eW2   = (const float*)d_in[5];
    const float* eb2   = (const float*)d_in[6];
    const float* lng   = (const float*)d_in[7];
    const float* lnb   = (const float*)d_in[8];
    const float* nW1   = (const float*)d_in[9];
    const float* nb1   = (const float*)d_in[10];
    const float* nW2   = (const float*)d_in[11];
    const float* nb2   = (const float*)d_in[12];
    const float* cW1   = (const float*)d_in[13];
    const float* cb1   = (const float*)d_in[14];
    const float* cW2   = (const float*)d_in[15];
    float* out = (float*)d_out;

    int E = in_sizes[2] / 2;
    int N = in_sizes[0] / 128;

    cudaFuncSetAttribute(edge_kernel, cudaFuncAttributeMaxDynamicSharedMemorySize, EDGE_SMEM_BYTES);
    cudaFuncSetAttribute(node_kernel, cudaFuncAttributeMaxDynamicSharedMemorySize, NODE_SMEM_BYTES);

    prep_kernel<<<(KPAD * 128 + 255) / 256, 256>>>(eW1, eW2);
    zero_kernel<<<256, 256>>>(N);
    geom_kernel<<<(E + 255) / 256, 256>>>(coord, ei, E);
    edge_kernel<<<(E + 127) / 128, 256, EDGE_SMEM_BYTES>>>(h, coord, ei, eb1, eb2, lng, lnb,
                                                           cW1, cb1, cW2, E);
    node_kernel<<<(N + 127) / 128, 256, NODE_SMEM_BYTES>>>(h, nW1, nb1, nW2, nb2, out, N);
    coordout_kernel<<<(3 * N + 255) / 256, 256>>>(coord, out + (size_t)N * 128, N);
}

// round 14
// speedup vs baseline: 1.2361x; 1.2361x over previous
#include <cuda_runtime.h>

typedef unsigned long long ull;
#define FEATC 268
#define KPAD  272

// ---------------- scratch: __device__ globals (no allocations) ----------------
__device__ float g_geom[(size_t)800000 * 12];  // radial,dist,dot,so3(9) per edge
__device__ float g_W1T[KPAD * 128];            // layer1 weights [f][n], heads concat, padded
__device__ float g_W2c[128 * 128];             // dense block-diag layer2 weights [k][n]
__device__ float g_agg[(size_t)50000 * 128];   // segment_sum(edge_feat)
__device__ float g_cacc[(size_t)50000 * 3];    // segment_sum(trans)

// ---------------- packed f32x2 helpers ----------------
__device__ __forceinline__ void fma2(ull& d, ull a, ull b) {
    asm("fma.rn.f32x2 %0, %1, %2, %0;" : "+l"(d) : "l"(a), "l"(b));
}
__device__ __forceinline__ ull bcast2(float x) {
    ull r; asm("mov.b64 %0, {%1, %1};" : "=l"(r) : "f"(x)); return r;
}
__device__ __forceinline__ ull pk2(float a, float b) {
    ull r; asm("mov.b64 %0, {%1, %2};" : "=l"(r) : "f"(a), "f"(b)); return r;
}
__device__ __forceinline__ float2 up2(ull v) {
    float2 f; asm("mov.b64 {%0, %1}, %2;" : "=f"(f.x), "=f"(f.y) : "l"(v)); return f;
}
__device__ __forceinline__ float silu_f(float x) { return x / (1.f + __expf(-x)); }

// Column mapping per thread: cols {tx4..tx4+3} and {64+tx4..64+tx4+3}
// acc[i][0] = cols (tx4, tx4+1); acc[i][1] = (tx4+2, tx4+3);
// acc[i][2] = (64+tx4, 64+tx4+1); acc[i][3] = (64+tx4+2, 64+tx4+3)

// ---- 8x8 micro-kernel: A k-major [8][128], B k-major [8][128] (one 8-k slab) ----
__device__ __forceinline__ void mm8(const float* __restrict__ A, const float* __restrict__ B,
                                    int m0, int tx4, ull acc[8][4]) {
#pragma unroll
    for (int kk = 0; kk < 8; kk++) {
        ulonglong2 q0 = *(const ulonglong2*)(B + kk * 128 + tx4);       // LDS.128, conflict-free
        ulonglong2 q1 = *(const ulonglong2*)(B + kk * 128 + 64 + tx4);
        ull b0 = q0.x, b1 = q0.y, b2 = q1.x, b3 = q1.y;
        float4 a0 = *(const float4*)(A + kk * 128 + m0);                // broadcast
        float4 a1 = *(const float4*)(A + kk * 128 + m0 + 4);
        float av[8] = {a0.x, a0.y, a0.z, a0.w, a1.x, a1.y, a1.z, a1.w};
#pragma unroll
        for (int i = 0; i < 8; i++) {
            ull ap = bcast2(av[i]);
            fma2(acc[i][0], ap, b0); fma2(acc[i][1], ap, b1);
            fma2(acc[i][2], ap, b2); fma2(acc[i][3], ap, b3);
        }
    }
}

// ---- same but A row-major pitch 132 (k window at k0), B k-major [128][128] ----
__device__ __forceinline__ void mm8_rm(const float* __restrict__ A, const float* __restrict__ B,
                                       int m0, int tx4, int k0, ull acc[8][4]) {
#pragma unroll
    for (int kk = 0; kk < 8; kk++) {
        int k = k0 + kk;
        ulonglong2 q0 = *(const ulonglong2*)(B + k * 128 + tx4);
        ulonglong2 q1 = *(const ulonglong2*)(B + k * 128 + 64 + tx4);
        ull b0 = q0.x, b1 = q0.y, b2 = q1.x, b3 = q1.y;
#pragma unroll
        for (int i = 0; i < 8; i++) {
            ull ap = bcast2(A[(m0 + i) * 132 + k]);                     // broadcast
            fma2(acc[i][0], ap, b0); fma2(acc[i][1], ap, b1);
            fma2(acc[i][2], ap, b2); fma2(acc[i][3], ap, b3);
        }
    }
}

// ---------------- prep: transpose eW1 -> [f][n]; densify eW2 block-diag ----------------
__global__ void prep_kernel(const float* __restrict__ eW1, const float* __restrict__ eW2) {
    int i = blockIdx.x * blockDim.x + threadIdx.x;
    if (i < KPAD * 128) {
        int f = i >> 7, n = i & 127;
        g_W1T[i] = (f < FEATC) ? eW1[(size_t)(n >> 5) * FEATC * 32 + (size_t)f * 32 + (n & 31)] : 0.f;
    }
    if (i < 128 * 128) {
        int k = i >> 7, n = i & 127;
        g_W2c[i] = ((k >> 5) == (n >> 5)) ? eW2[(k >> 5) * 1024 + (k & 31) * 32 + (n & 31)] : 0.f;
    }
}

__global__ void zero_kernel(int N) {
    int total = N * 128 + N * 3;
    for (int i = blockIdx.x * blockDim.x + threadIdx.x; i < total; i += gridDim.x * blockDim.x) {
        if (i < N * 128) g_agg[i] = 0.f;
        else g_cacc[i - N * 128] = 0.f;
    }
}

// ---------------- per-edge geometry ----------------
__global__ void geom_kernel(const float* __restrict__ coord, const int* __restrict__ ei, int E) {
    int e = blockIdx.x * blockDim.x + threadIdx.x;
    if (e >= E) return;
    int r = ei[e], c = ei[E + e];
    float cix = coord[r * 3], ciy = coord[r * 3 + 1], ciz = coord[r * 3 + 2];
    float ckx = coord[c * 3], cky = coord[c * 3 + 1], ckz = coord[c * 3 + 2];
    float dx = cix - ckx, dy = ciy - cky, dz = ciz - ckz;
    float radial = dx * dx + dy * dy + dz * dz;
    float dist = sqrtf(radial);
    float dotv = cix * ckx + ciy * cky + ciz * ckz;
    float inva = 1.f / (dist + 1e-8f);
    float ax = dx * inva, ay = dy * inva, az = dz * inva;
    float px = ciy * ckz - ciz * cky;
    float py = ciz * ckx - cix * ckz;
    float pz = cix * cky - ciy * ckx;
    float nb = sqrtf(px * px + py * py + pz * pz);
    float invb = 1.f / (nb + 1e-8f);
    float bx = px * invb, by = py * invb, bz = pz * invb;
    float cx = ay * bz - az * by;
    float cy = az * bx - ax * bz;
    float cz = ax * by - ay * bx;
    float na_n = sqrtf(ax * ax + ay * ay + az * az);
    float nb_n = sqrtf(bx * bx + by * by + bz * bz);
    float nc_n = sqrtf(cx * cx + cy * cy + cz * cz);
    if ((na_n < 1e-6f) || (nb_n < 1e-6f) || (nc_n < 1e-6f)) {
        ax = 1.f; ay = 0.f; az = 0.f; bx = 0.f; by = 1.f; bz = 0.f; cx = 0.f; cy = 0.f; cz = 1.f;
    }
    float* g = g_geom + (size_t)e * 12;
    g[0] = radial; g[1] = dist; g[2] = dotv;
    g[3] = ax; g[4] = bx; g[5] = cx;
    g[6] = ay; g[7] = by; g[8] = cy;
    g[9] = az; g[10] = bz; g[11] = cz;
}

// ---------------- edge mega-kernel ----------------
// smem floats: As[2][1024] Bs[2][1024] xb[128*132] B2[128*128] rS[128*17] rQ[128*17]
//              erow[128]i ecol[128]i cw2s[128]  -> 42112 words = 168448 B
#define EDGE_SMEM_BYTES (42112 * 4)
__global__ void __launch_bounds__(256, 1)
edge_kernel(const float* __restrict__ h, const float* __restrict__ coord,
            const int* __restrict__ ei,
            const float* __restrict__ eb1, const float* __restrict__ eb2,
            const float* __restrict__ lng, const float* __restrict__ lnb,
            const float* __restrict__ cW1, const float* __restrict__ cb1,
            const float* __restrict__ cW2, int E) {
    extern __shared__ float sm[];
    float* As = sm;                 // 2 x 1024
    float* Bs = sm + 2048;          // 2 x 1024
    float* xb = sm + 4096;          // [128][132] row-major
    float* B2 = sm + 20992;         // [128][128]
    float* rS = sm + 37376;         // [128][17]
    float* rQ = sm + 39552;
    int*  erow = (int*)(sm + 41728);
    int*  ecol = erow + 128;
    float* cw2s = sm + 41984;

    int tid = threadIdx.x;
    int tx = tid & 15, ty = tid >> 4;
    int m0 = ty * 8, tx4 = tx * 4;
    int e0 = blockIdx.x * 128;

    if (tid < 128) {
        int e = min(e0 + tid, E - 1);
        erow[tid] = ei[e];
        ecol[tid] = ei[E + e];
        cw2s[tid] = cW2[tid];
    }
    for (int i = tid; i < 16384; i += 256) B2[i] = g_W2c[i];
    __syncthreads();

    const float* hrow = h;
    const float* hcol = h;
    size_t egm = 0;
    if (tid < 128) {
        hrow = h + (size_t)erow[tid] * 128;
        hcol = h + (size_t)ecol[tid] * 128;
        egm = (size_t)min(e0 + tid, E - 1);
    }

    ull acc[8][4];
#pragma unroll
    for (int i = 0; i < 8; i++) { acc[i][0] = acc[i][1] = acc[i][2] = acc[i][3] = 0ULL; }

    // ---- GEMM1: feats[128,272] x W1T[272,128], double-buffered, 1 sync/slab ----
    const int STEPS = KPAD / 8;  // 34
    float lr[8];
    // prologue load slab 0
    {
        if (tid < 128) {
            float4 v0 = ((const float4*)hrow)[0];
            float4 v1 = ((const float4*)hrow)[1];
            lr[0] = v0.x; lr[1] = v0.y; lr[2] = v0.z; lr[3] = v0.w;
            lr[4] = v1.x; lr[5] = v1.y; lr[6] = v1.z; lr[7] = v1.w;
        } else {
            int n = tid - 128;
#pragma unroll
            for (int kk = 0; kk < 8; kk++) lr[kk] = g_W1T[kk * 128 + n];
        }
    }
    for (int s = 0; s < STEPS; s++) {
        // store current slab (lr) into buffer s&1
        {
            float* dst = ((tid < 128) ? As : Bs) + (s & 1) * 1024;
            int o = tid & 127;
#pragma unroll
            for (int kk = 0; kk < 8; kk++) dst[kk * 128 + o] = lr[kk];
        }
        // prefetch next slab
        if (s + 1 < STEPS) {
            int k0 = (s + 1) * 8;
            if (tid < 128) {
                if (k0 < 256) {
                    const float* base = (k0 < 128) ? (hrow + k0) : (hcol + (k0 - 128));
                    float4 v0 = ((const float4*)base)[0];
                    float4 v1 = ((const float4*)base)[1];
                    lr[0] = v0.x; lr[1] = v0.y; lr[2] = v0.z; lr[3] = v0.w;
                    lr[4] = v1.x; lr[5] = v1.y; lr[6] = v1.z; lr[7] = v1.w;
                } else {
#pragma unroll
                    for (int kk = 0; kk < 8; kk++) {
                        int f = k0 + kk;
                        lr[kk] = (f < FEATC) ? g_geom[egm * 12 + (f - 256)] : 0.f;
                    }
                }
            } else {
                int n = tid - 128;
#pragma unroll
                for (int kk = 0; kk < 8; kk++) lr[kk] = g_W1T[(k0 + kk) * 128 + n];
            }
        }
        __syncthreads();
        mm8(As + (s & 1) * 1024, Bs + (s & 1) * 1024, m0, tx4, acc);
    }

    // x1 = silu(acc + eb1) -> xb row-major (split columns)
#pragma unroll
    for (int i = 0; i < 8; i++) {
        float4 w0, w1;
        float2 v0 = up2(acc[i][0]), v1 = up2(acc[i][1]), v2 = up2(acc[i][2]), v3 = up2(acc[i][3]);
        w0.x = silu_f(v0.x + eb1[tx4 + 0]);      w0.y = silu_f(v0.y + eb1[tx4 + 1]);
        w0.z = silu_f(v1.x + eb1[tx4 + 2]);      w0.w = silu_f(v1.y + eb1[tx4 + 3]);
        w1.x = silu_f(v2.x + eb1[64 + tx4 + 0]); w1.y = silu_f(v2.y + eb1[64 + tx4 + 1]);
        w1.z = silu_f(v3.x + eb1[64 + tx4 + 2]); w1.w = silu_f(v3.y + eb1[64 + tx4 + 3]);
        *(float4*)(xb + (m0 + i) * 132 + tx4)      = w0;
        *(float4*)(xb + (m0 + i) * 132 + 64 + tx4) = w1;
    }
    __syncthreads();

    // ---- GEMM2 (dense block-diag W2) ----
#pragma unroll
    for (int i = 0; i < 8; i++) { acc[i][0] = acc[i][1] = acc[i][2] = acc[i][3] = 0ULL; }
    for (int k0 = 0; k0 < 128; k0 += 8) mm8_rm(xb, B2, m0, tx4, k0, acc);

    // add eb2, accumulate LN stats, keep biased values packed in acc
#pragma unroll
    for (int i = 0; i < 8; i++) {
        float s_ = 0.f, q_ = 0.f;
#pragma unroll
        for (int jp = 0; jp < 4; jp++) {
            int c = (jp < 2) ? (tx4 + 2 * jp) : (64 + tx4 + 2 * (jp - 2));
            float2 v = up2(acc[i][jp]);
            float a0 = v.x + eb2[c];
            float a1 = v.y + eb2[c + 1];
            acc[i][jp] = pk2(a0, a1);
            s_ += a0 + a1; q_ += a0 * a0 + a1 * a1;
        }
        rS[(m0 + i) * 17 + tx] = s_;
        rQ[(m0 + i) * 17 + tx] = q_;
    }
    __syncthreads();

    // ---- LayerNorm -> xb (+ agg atomics), reload B2 <- cW1 ----
#pragma unroll
    for (int i = 0; i < 8; i++) {
        float s_ = 0.f, q_ = 0.f;
#pragma unroll
        for (int t = 0; t < 16; t++) { s_ += rS[(m0 + i) * 17 + t]; q_ += rQ[(m0 + i) * 17 + t]; }
        float mu = s_ * (1.f / 128.f);
        float var = q_ * (1.f / 128.f) - mu * mu;
        float rstd = rsqrtf(var + 1e-5f);
        float vals[8];
#pragma unroll
        for (int jp = 0; jp < 4; jp++) {
            int c = (jp < 2) ? (tx4 + 2 * jp) : (64 + tx4 + 2 * (jp - 2));
            float2 v = up2(acc[i][jp]);
            vals[2 * jp]     = (v.x - mu) * rstd * lng[c] + lnb[c];
            vals[2 * jp + 1] = (v.y - mu) * rstd * lng[c + 1] + lnb[c + 1];
        }
        *(float4*)(xb + (m0 + i) * 132 + tx4)      = make_float4(vals[0], vals[1], vals[2], vals[3]);
        *(float4*)(xb + (m0 + i) * 132 + 64 + tx4) = make_float4(vals[4], vals[5], vals[6], vals[7]);
        if (e0 + m0 + i < E) {
            size_t rbase = (size_t)erow[m0 + i] * 128;
#pragma unroll
            for (int j = 0; j < 4; j++) atomicAdd(&g_agg[rbase + tx4 + j], vals[j]);
#pragma unroll
            for (int j = 0; j < 4; j++) atomicAdd(&g_agg[rbase + 64 + tx4 + j], vals[4 + j]);
        }
    }
    for (int i = tid; i < 16384; i += 256) B2[i] = cW1[i];
    __syncthreads();

    // ---- GEMM3: hid = edge_feat @ cW1 ; w = silu(hid+cb1) . cW2 ----
#pragma unroll
    for (int i = 0; i < 8; i++) { acc[i][0] = acc[i][1] = acc[i][2] = acc[i][3] = 0ULL; }
    for (int k0 = 0; k0 < 128; k0 += 8) mm8_rm(xb, B2, m0, tx4, k0, acc);
#pragma unroll
    for (int i = 0; i < 8; i++) {
        float p = 0.f;
#pragma unroll
        for (int jp = 0; jp < 4; jp++) {
            int c = (jp < 2) ? (tx4 + 2 * jp) : (64 + tx4 + 2 * (jp - 2));
            float2 v = up2(acc[i][jp]);
            p += silu_f(v.x + cb1[c]) * cw2s[c];
            p += silu_f(v.y + cb1[c + 1]) * cw2s[c + 1];
        }
        rS[(m0 + i) * 17 + tx] = p;
    }
    __syncthreads();
    if (tid < 128 && e0 + tid < E) {
        float w = 0.f;
#pragma unroll
        for (int t = 0; t < 16; t++) w += rS[tid * 17 + t];
        int r = erow[tid], c = ecol[tid];
        float dx = coord[r * 3]     - coord[c * 3];
        float dy = coord[r * 3 + 1] - coord[c * 3 + 1];
        float dz = coord[r * 3 + 2] - coord[c * 3 + 2];
        atomicAdd(&g_cacc[r * 3 + 0], dx * w);
        atomicAdd(&g_cacc[r * 3 + 1], dy * w);
        atomicAdd(&g_cacc[r * 3 + 2], dz * w);
    }
}

// ---------------- node kernel: h_out = h + MLP([h, agg]) ----------------
// smem floats: As[2][1024] Bs[2][1024] xb[128*132] B2[128*128] = 37376 words
#define NODE_SMEM_BYTES (37376 * 4)
__global__ void __launch_bounds__(256, 1)
node_kernel(const float* __restrict__ h,
            const float* __restrict__ nW1, const float* __restrict__ nb1,
            const float* __restrict__ nW2, const float* __restrict__ nb2,
            float* __restrict__ out, int N) {
    extern __shared__ float sm[];
    float* As = sm;
    float* Bs = sm + 2048;
    float* xb = sm + 4096;
    float* B2 = sm + 20992;

    int tid = threadIdx.x;
    int tx = tid & 15, ty = tid >> 4;
    int m0 = ty * 8, tx4 = tx * 4;
    int v0base = blockIdx.x * 128;

    for (int i = tid; i < 16384; i += 256) B2[i] = nW2[i];

    size_t node = (size_t)min(v0base + (tid & 127), N - 1);

    ull acc[8][4];
#pragma unroll
    for (int i = 0; i < 8; i++) { acc[i][0] = acc[i][1] = acc[i][2] = acc[i][3] = 0ULL; }

    float lr[8];
    // prologue slab 0
    if (tid < 128) {
        const float4* base = (const float4*)(h + node * 128);
        float4 v0 = base[0], v1 = base[1];
        lr[0] = v0.x; lr[1] = v0.y; lr[2] = v0.z; lr[3] = v0.w;
        lr[4] = v1.x; lr[5] = v1.y; lr[6] = v1.z; lr[7] = v1.w;
    } else {
        int n = tid - 128;
#pragma unroll
        for (int kk = 0; kk < 8; kk++) lr[kk] = nW1[kk * 128 + n];
    }
    // first sync: also covers B2 fill
    for (int s = 0; s < 32; s++) {
        {
            float* dst = ((tid < 128) ? As : Bs) + (s & 1) * 1024;
            int o = tid & 127;
#pragma unroll
            for (int kk = 0; kk < 8; kk++) dst[kk * 128 + o] = lr[kk];
        }
        if (s + 1 < 32) {
            int k0 = (s + 1) * 8;
            if (tid < 128) {
                const float* base = (k0 < 128) ? (h + node * 128 + k0)
                                               : (g_agg + node * 128 + (k0 - 128));
                float4 v0 = ((const float4*)base)[0];
                float4 v1 = ((const float4*)base)[1];
                lr[0] = v0.x; lr[1] = v0.y; lr[2] = v0.z; lr[3] = v0.w;
                lr[4] = v1.x; lr[5] = v1.y; lr[6] = v1.z; lr[7] = v1.w;
            } else {
                int n = tid - 128;
#pragma unroll
                for (int kk = 0; kk < 8; kk++) lr[kk] = nW1[(k0 + kk) * 128 + n];
            }
        }
        __syncthreads();
        mm8(As + (s & 1) * 1024, Bs + (s & 1) * 1024, m0, tx4, acc);
    }
#pragma unroll
    for (int i = 0; i < 8; i++) {
        float4 w0, w1;
        float2 v0 = up2(acc[i][0]), v1 = up2(acc[i][1]), v2 = up2(acc[i][2]), v3 = up2(acc[i][3]);
        w0.x = silu_f(v0.x + nb1[tx4 + 0]);      w0.y = silu_f(v0.y + nb1[tx4 + 1]);
        w0.z = silu_f(v1.x + nb1[tx4 + 2]);      w0.w = silu_f(v1.y + nb1[tx4 + 3]);
        w1.x = silu_f(v2.x + nb1[64 + tx4 + 0]); w1.y = silu_f(v2.y + nb1[64 + tx4 + 1]);
        w1.z = silu_f(v3.x + nb1[64 + tx4 + 2]); w1.w = silu_f(v3.y + nb1[64 + tx4 + 3]);
        *(float4*)(xb + (m0 + i) * 132 + tx4)      = w0;
        *(float4*)(xb + (m0 + i) * 132 + 64 + tx4) = w1;
    }
    __syncthreads();

#pragma unroll
    for (int i = 0; i < 8; i++) { acc[i][0] = acc[i][1] = acc[i][2] = acc[i][3] = 0ULL; }
    for (int k0 = 0; k0 < 128; k0 += 8) mm8_rm(xb, B2, m0, tx4, k0, acc);

#pragma unroll
    for (int i = 0; i < 8; i++) {
        int nd = v0base + m0 + i;
        if (nd >= N) continue;
        float4 h0 = *(const float4*)(h + (size_t)nd * 128 + tx4);
        float4 h1 = *(const float4*)(h + (size_t)nd * 128 + 64 + tx4);
        float2 v0 = up2(acc[i][0]), v1 = up2(acc[i][1]), v2 = up2(acc[i][2]), v3 = up2(acc[i][3]);
        float4 o0, o1;
        o0.x = v0.x + nb2[tx4 + 0] + h0.x;      o0.y = v0.y + nb2[tx4 + 1] + h0.y;
        o0.z = v1.x + nb2[tx4 + 2] + h0.z;      o0.w = v1.y + nb2[tx4 + 3] + h0.w;
        o1.x = v2.x + nb2[64 + tx4 + 0] + h1.x; o1.y = v2.y + nb2[64 + tx4 + 1] + h1.y;
        o1.z = v3.x + nb2[64 + tx4 + 2] + h1.z; o1.w = v3.y + nb2[64 + tx4 + 3] + h1.w;
        *(float4*)(out + (size_t)nd * 128 + tx4)      = o0;
        *(float4*)(out + (size_t)nd * 128 + 64 + tx4) = o1;
    }
}

__global__ void coordout_kernel(const float* __restrict__ coord, float* __restrict__ out, int N) {
    int i = blockIdx.x * blockDim.x + threadIdx.x;
    if (i < 3 * N) out[i] = coord[i] + g_cacc[i];
}

extern "C" void kernel_launch(void* const* d_in, const int* in_sizes, int n_in,
                              void* d_out, int out_size) {
    const float* h     = (const float*)d_in[0];
    const float* coord = (const float*)d_in[1];
    const int*   ei    = (const int*)d_in[2];
    const float* eW1   = (const float*)d_in[3];
    const float* eb1   = (const float*)d_in[4];
    const float* eW2   = (const float*)d_in[5];
    const float* eb2   = (const float*)d_in[6];
    const float* lng   = (const float*)d_in[7];
    const float* lnb   = (const float*)d_in[8];
    const float* nW1   = (const float*)d_in[9];
    const float* nb1   = (const float*)d_in[10];
    const float* nW2   = (const float*)d_in[11];
    const float* nb2   = (const float*)d_in[12];
    const float* cW1   = (const float*)d_in[13];
    const float* cb1   = (const float*)d_in[14];
    const float* cW2   = (const float*)d_in[15];
    float* out = (float*)d_out;

    int E = in_sizes[2] / 2;
    int N = in_sizes[0] / 128;

    cudaFuncSetAttribute(edge_kernel, cudaFuncAttributeMaxDynamicSharedMemorySize, EDGE_SMEM_BYTES);
    cudaFuncSetAttribute(node_kernel, cudaFuncAttributeMaxDynamicSharedMemorySize, NODE_SMEM_BYTES);

    prep_kernel<<<(KPAD * 128 + 255) / 256, 256>>>(eW1, eW2);
    zero_kernel<<<256, 256>>>(N);
    geom_kernel<<<(E + 255) / 256, 256>>>(coord, ei, E);
    edge_kernel<<<(E + 127) / 128, 256, EDGE_SMEM_BYTES>>>(h, coord, ei, eb1, eb2, lng, lnb,
                                                           cW1, cb1, cW2, E);
    node_kernel<<<(N + 127) / 128, 256, NODE_SMEM_BYTES>>>(h, nW1, nb1, nW2, nb2, out, N);
    coordout_kernel<<<(3 * N + 255) / 256, 256>>>(coord, out + (size_t)N * 128, N);
}